// round 15
// baseline (speedup 1.0000x reference)
#include <cuda_runtime.h>
#include <cuda_bf16.h>
#include <math.h>
#include <stdint.h>

#define Bq 64
#define Sq 128
#define Eq 512
#define Hq 1024
#define Vq 50257
#define K2q 2560        /* E + H + H : fused gates K */
#define G4q (4 * Hq)
#define SBq (Sq * Bq)
#define NSLOT 32
#define LSC 6304

// ---------------- scratch (static device globals; no runtime allocation) ----
__device__ float g_hW[Bq * Hq];
__device__ float g_spart[NSLOT * SBq];
__device__ float g_ctx[Bq * Hq];
__device__ float g_x2[Bq * K2q];
__device__ float g_gates[Bq * G4q];
__device__ float g_lsm[Bq * 8];
__device__ float g_lss[Bq * 8];
__device__ uint2 g_es[SBq * 512];      // enc pre-split: hi/lo bf16x2 pairs
__device__ uint2 g_us[Hq * 512];       // U pre-split

// ---------------- helpers ---------------------------------------------------
__device__ __forceinline__ uint32_t smem_u32(const void* p)
{
    uint32_t a;
    asm("{ .reg .u64 t; cvta.to.shared.u64 t, %1; cvt.u32.u64 %0, t; }"
        : "=r"(a) : "l"(p));
    return a;
}

__device__ __forceinline__ void split_bf16(float x, float& hi, float& lo)
{
    hi = __bfloat162float(__float2bfloat16(x));
    lo = x - hi;
}

__device__ __forceinline__ unsigned pack2(float e0, float e1)
{
    unsigned r;
    asm("cvt.rn.bf16x2.f32 %0, %1, %2;" : "=r"(r) : "f"(e1), "f"(e0));
    return r;
}

__device__ __forceinline__ void mma_bf16(float c[4], const unsigned a[4],
                                         const unsigned b[2])
{
    asm volatile(
        "mma.sync.aligned.m16n8k16.row.col.f32.bf16.bf16.f32 "
        "{%0,%1,%2,%3}, {%4,%5,%6,%7}, {%8,%9}, {%0,%1,%2,%3};"
        : "+f"(c[0]), "+f"(c[1]), "+f"(c[2]), "+f"(c[3])
        : "r"(a[0]), "r"(a[1]), "r"(a[2]), "r"(a[3]), "r"(b[0]), "r"(b[1]));
}

__device__ __forceinline__ float tanh_fast(float x)
{
    float cx = fminf(fmaxf(x, -15.f), 15.f);
    float e = __expf(2.f * cx);
    return __fdividef(e - 1.f, e + 1.f);
}

__device__ __forceinline__ void cp16(uint32_t dst, const void* src)
{
    asm volatile("cp.async.cg.shared.global [%0], [%1], 16;"
                 :: "r"(dst), "l"(src) : "memory");
}
__device__ __forceinline__ void cp_commit()
{
    asm volatile("cp.async.commit_group;" ::: "memory");
}
template <int N>
__device__ __forceinline__ void cp_wait()
{
    asm volatile("cp.async.wait_group %0;" :: "n"(N) : "memory");
}

// ================== pre-split kernels: fp32 -> hi/lo bf16x2 uint2 ===========
__global__ void presplit_kernel_enc(const float* __restrict__ src)
{
    size_t i = (size_t)blockIdx.x * 256 + threadIdx.x;   // float4 index
    float4 v = reinterpret_cast<const float4*>(src)[i];
    float hx, lx, hy, ly, hz, lz, hw, lw;
    split_bf16(v.x, hx, lx); split_bf16(v.y, hy, ly);
    split_bf16(v.z, hz, lz); split_bf16(v.w, hw, lw);
    g_es[2 * i]     = make_uint2(pack2(hx, hy), pack2(lx, ly));
    g_es[2 * i + 1] = make_uint2(pack2(hz, hw), pack2(lz, lw));
}

__global__ void presplit_kernel_u(const float* __restrict__ src)
{
    size_t i = (size_t)blockIdx.x * 256 + threadIdx.x;
    float4 v = reinterpret_cast<const float4*>(src)[i];
    float hx, lx, hy, ly, hz, lz, hw, lw;
    split_bf16(v.x, hx, lx); split_bf16(v.y, hy, ly);
    split_bf16(v.z, hz, lz); split_bf16(v.w, hw, lw);
    g_us[2 * i]     = make_uint2(pack2(hx, hy), pack2(lx, ly));
    g_us[2 * i + 1] = make_uint2(pack2(hz, hw), pack2(lz, lw));
}

// ============ T GEMM: pre-split, 4-stage cp.async, BK=16, immediate LDS =====
// T = enc[8192,1024] @ U[1024,1024]^T; score partials out (32 slots).
// BM=128, BN=64, 8 pairs/chunk (64 chunks); warp grid 4(M)x2(N), tile 32x32.
// ROWP=10 -> fragment LDS.64 conflict-free AND all offsets compile-time.
#define TS_ROWP 10                      /* uint2 per row (8 data + 2 pad) */
#define TS_B (128 * TS_ROWP)            /* B offset in uint2 = 1280 */
#define TS_STG (192 * TS_ROWP)          /* uint2 per stage = 1920 */
#define TS_STGB (TS_STG * 8)            /* 15360 B */
#define TS_SMEM (4 * TS_STGB)           /* 61440 B */

__global__ void __launch_bounds__(256, 2)
tgemm_score_kernel(const float* __restrict__ Ub, const float* __restrict__ v)
{
    extern __shared__ uint2 smt[];
    constexpr int MI = 2, NI = 4;

    const int tid = threadIdx.x;
    const int lane = tid & 31;
    const int w = tid >> 5;
    const int lane4 = lane >> 2;
    const int lanek = lane & 3;
    const int warp_m = (w & 3) * 32;
    const int warp_n = (w >> 2) * 32;
    const int m0 = blockIdx.y * 128;
    const int n0 = blockIdx.x * 64;

    // ---- hoisted loader addressing: A 512 slots/256thr = 2, B 256 = 1 -----
    const uint32_t sb0 = smem_u32(smt);
    uint32_t adst[2], bdst;
    const uint2* asrc[2];
    const uint2* bsrc;
#pragma unroll
    for (int u = 0; u < 2; u++) {
        int i = tid + 256 * u;
        int row = i >> 2, pe = (i & 3) * 2;
        adst[u] = (uint32_t)(row * TS_ROWP + pe) * 8;
        asrc[u] = g_es + (size_t)(m0 + row) * 512 + pe;
    }
    {
        int row = tid >> 2, pe = (tid & 3) * 2;
        bdst = (uint32_t)(TS_B + row * TS_ROWP + pe) * 8;
        bsrc = g_us + (size_t)(n0 + row) * 512 + pe;
    }

    float acc[MI][NI][4];
#pragma unroll
    for (int i = 0; i < MI; i++)
#pragma unroll
        for (int j = 0; j < NI; j++)
#pragma unroll
            for (int q = 0; q < 4; q++) acc[i][j][q] = 0.f;

    auto issue = [&](int ch) {
        uint32_t base = sb0 + (uint32_t)(ch & 3) * TS_STGB;
        int ko = ch * 8;
        cp16(base + adst[0], asrc[0] + ko);
        cp16(base + adst[1], asrc[1] + ko);
        cp16(base + bdst, bsrc + ko);
        cp_commit();
    };

    issue(0); issue(1); issue(2);

    // per-warp fragment bases (uint2 index within a stage)
    const int abase = (warp_m + lane4) * TS_ROWP + lanek;
    const int bbase = TS_B + (warp_n + lane4) * TS_ROWP + lanek;

    for (int ch = 0; ch < 64; ch++) {
        cp_wait<2>();
        __syncthreads();
        const uint2* stg = smt + (ch & 3) * TS_STG;
        const uint2* pa = stg + abase;
        const uint2* pb = stg + bbase;

        unsigned ah[MI][4], al[MI][4], bh[NI][2], bl[NI][2];
#pragma unroll
        for (int i = 0; i < MI; i++) {
            uint2 t0 = pa[i * 160];          // +i*16 rows
            uint2 t1 = pa[i * 160 + 80];     // +8 rows
            uint2 t2 = pa[i * 160 + 4];      // +4 pairs (k+8)
            uint2 t3 = pa[i * 160 + 84];
            ah[i][0] = t0.x; al[i][0] = t0.y;
            ah[i][1] = t1.x; al[i][1] = t1.y;
            ah[i][2] = t2.x; al[i][2] = t2.y;
            ah[i][3] = t3.x; al[i][3] = t3.y;
        }
#pragma unroll
        for (int j = 0; j < NI; j++) {
            uint2 t0 = pb[j * 80];           // +j*8 rows
            uint2 t1 = pb[j * 80 + 4];
            bh[j][0] = t0.x; bl[j][0] = t0.y;
            bh[j][1] = t1.x; bl[j][1] = t1.y;
        }
#pragma unroll
        for (int i = 0; i < MI; i++)
#pragma unroll
            for (int j = 0; j < NI; j++) {
                mma_bf16(acc[i][j], ah[i], bl[j]);
                mma_bf16(acc[i][j], al[i], bh[j]);
                mma_bf16(acc[i][j], ah[i], bh[j]);
            }

        if (ch + 3 < 64) issue(ch + 3);
        else cp_commit();               // keep group count consistent
    }

    // ---- fused score epilogue over this warp's 32 columns ------------------
    float vv[NI][2], uu[NI][2];
#pragma unroll
    for (int j = 0; j < NI; j++)
#pragma unroll
        for (int qc = 0; qc < 2; qc++) {
            int c = n0 + warp_n + j * 8 + 2 * lanek + qc;
            vv[j][qc] = v[c];
            uu[j][qc] = Ub[c];
        }

    const int slot = blockIdx.x * 2 + (w >> 2);
#pragma unroll
    for (int i = 0; i < MI; i++)
#pragma unroll
        for (int qr = 0; qr < 2; qr++) {
            int row = m0 + warp_m + i * 16 + lane4 + qr * 8;
            int b = row & (Bq - 1);
            const float* hwr = g_hW + (size_t)b * Hq + n0 + warp_n + 2 * lanek;
            float part = 0.f;
#pragma unroll
            for (int j = 0; j < NI; j++)
#pragma unroll
                for (int qc = 0; qc < 2; qc++) {
                    float t = acc[i][j][2 * qr + qc] + uu[j][qc]
                              + hwr[j * 8 + qc];
                    part += vv[j][qc] * tanh_fast(t);
                }
            part += __shfl_xor_sync(0xffffffffu, part, 1);
            part += __shfl_xor_sync(0xffffffffu, part, 2);
            if (lanek == 0)
                g_spart[(size_t)slot * SBq + row] = part;
        }
}

// ================== 3xBF16 GEMM template (hW) ===============================
template <int BM, int BN, int BK, int WM, int WN>
__global__ void __launch_bounds__(256)
mma3bf_gemm_nt(const float* __restrict__ A, const float* __restrict__ Bm,
               float* __restrict__ C, int M, int N, int K,
               const float* __restrict__ bias)
{
    constexpr int MI = WM / 16;
    constexpr int NI = WN / 8;
    constexpr int PP = BK / 2;
    constexpr int KPP = PP + 4;
    constexpr int F4R = BK / 4;
    constexpr int RPP = 256 / F4R;

    __shared__ uint2 Aa[BM][KPP];
    __shared__ uint2 Ba[BN][KPP];

    const int tid = threadIdx.x;
    const int lane = tid & 31;
    const int w = tid >> 5;
    const int warp_m = (w % (BM / WM)) * WM;
    const int warp_n = (w / (BM / WM)) * WN;
    const int m0 = blockIdx.y * BM;
    const int n0 = blockIdx.x * BN;
    const int lrow = tid / F4R;
    const int lk4 = (tid % F4R) * 4;
    const int lp = lk4 >> 1;

    float acc[MI][NI][4];
#pragma unroll
    for (int i = 0; i < MI; i++)
#pragma unroll
        for (int j = 0; j < NI; j++)
#pragma unroll
            for (int q = 0; q < 4; q++) acc[i][j][q] = 0.f;

    for (int k0 = 0; k0 < K; k0 += BK) {
#pragma unroll
        for (int r = lrow; r < BM; r += RPP) {
            float4 vv = *reinterpret_cast<const float4*>(
                A + (size_t)(m0 + r) * K + k0 + lk4);
            float hx, lx, hy, ly, hz, lz, hw, lw;
            split_bf16(vv.x, hx, lx); split_bf16(vv.y, hy, ly);
            split_bf16(vv.z, hz, lz); split_bf16(vv.w, hw, lw);
            Aa[r][lp]     = make_uint2(pack2(hx, hy), pack2(lx, ly));
            Aa[r][lp + 1] = make_uint2(pack2(hz, hw), pack2(lz, lw));
        }
#pragma unroll
        for (int r = lrow; r < BN; r += RPP) {
            float4 vv = make_float4(0.f, 0.f, 0.f, 0.f);
            if (n0 + r < N)
                vv = *reinterpret_cast<const float4*>(
                    Bm + (size_t)(n0 + r) * K + k0 + lk4);
            float hx, lx, hy, ly, hz, lz, hw, lw;
            split_bf16(vv.x, hx, lx); split_bf16(vv.y, hy, ly);
            split_bf16(vv.z, hz, lz); split_bf16(vv.w, hw, lw);
            Ba[r][lp]     = make_uint2(pack2(hx, hy), pack2(lx, ly));
            Ba[r][lp + 1] = make_uint2(pack2(hz, hw), pack2(lz, lw));
        }
        __syncthreads();

#pragma unroll
        for (int kk = 0; kk < PP; kk += 8) {
            unsigned ah[MI][4], al[MI][4], bh[NI][2], bl[NI][2];
#pragma unroll
            for (int i = 0; i < MI; i++) {
                int r = warp_m + i * 16 + (lane >> 2);
                int cb = kk + (lane & 3);
                uint2 t0 = Aa[r][cb];      ah[i][0] = t0.x; al[i][0] = t0.y;
                uint2 t1 = Aa[r + 8][cb];  ah[i][1] = t1.x; al[i][1] = t1.y;
                uint2 t2 = Aa[r][cb + 4];  ah[i][2] = t2.x; al[i][2] = t2.y;
                uint2 t3 = Aa[r + 8][cb + 4]; ah[i][3] = t3.x; al[i][3] = t3.y;
            }
#pragma unroll
            for (int j = 0; j < NI; j++) {
                int r = warp_n + j * 8 + (lane >> 2);
                int cb = kk + (lane & 3);
                uint2 t0 = Ba[r][cb];      bh[j][0] = t0.x; bl[j][0] = t0.y;
                uint2 t1 = Ba[r][cb + 4];  bh[j][1] = t1.x; bl[j][1] = t1.y;
            }
#pragma unroll
            for (int i = 0; i < MI; i++)
#pragma unroll
                for (int j = 0; j < NI; j++) {
                    mma_bf16(acc[i][j], ah[i], bl[j]);
                    mma_bf16(acc[i][j], al[i], bh[j]);
                    mma_bf16(acc[i][j], ah[i], bh[j]);
                }
        }
        __syncthreads();
    }

#pragma unroll
    for (int i = 0; i < MI; i++)
#pragma unroll
        for (int j = 0; j < NI; j++) {
            int row = m0 + warp_m + i * 16 + (lane >> 2);
            int col = n0 + warp_n + j * 8 + 2 * (lane & 3);
#pragma unroll
            for (int q = 0; q < 4; q++) {
                int gr = row + (q >> 1) * 8;
                int gc = col + (q & 1);
                if (gc < N) {
                    float r = acc[i][j][q];
                    if (bias) r += bias[gc];
                    C[(size_t)gr * N + gc] = r;
                }
            }
        }
}

// ============ fused gates GEMM: [x2] @ [W_ih;W_hh]^T, K=2560, 3xBF16 ========
__global__ void __launch_bounds__(256)
gates_kernel(const float* __restrict__ W1, const float* __restrict__ W2,
             const float* __restrict__ b1, const float* __restrict__ b2)
{
    constexpr int BM = 64, BN = 64, BK = 32;
    constexpr int MI = 2, NI = 2;
    constexpr int PP = 16, KPP = 20;

    __shared__ uint2 Aa[BM][KPP];
    __shared__ uint2 Ba[BN][KPP];

    const int tid = threadIdx.x;
    const int lane = tid & 31;
    const int w = tid >> 5;
    const int warp_m = (w % 2) * 32;
    const int warp_n = (w / 2) * 16;
    const int n0 = blockIdx.x * BN;
    const int lrow = tid >> 3;
    const int lk4 = (tid & 7) * 4;
    const int lp = lk4 >> 1;

    float acc[MI][NI][4];
#pragma unroll
    for (int i = 0; i < MI; i++)
#pragma unroll
        for (int j = 0; j < NI; j++)
#pragma unroll
            for (int q = 0; q < 4; q++) acc[i][j][q] = 0.f;

    for (int k0 = 0; k0 < K2q; k0 += BK) {
#pragma unroll
        for (int r = lrow; r < BM; r += 32) {
            float4 vv = *reinterpret_cast<const float4*>(
                g_x2 + (size_t)r * K2q + k0 + lk4);
            float hx, lx, hy, ly, hz, lz, hw, lw;
            split_bf16(vv.x, hx, lx); split_bf16(vv.y, hy, ly);
            split_bf16(vv.z, hz, lz); split_bf16(vv.w, hw, lw);
            Aa[r][lp]     = make_uint2(pack2(hx, hy), pack2(lx, ly));
            Aa[r][lp + 1] = make_uint2(pack2(hz, hw), pack2(lz, lw));
        }
#pragma unroll
        for (int r = lrow; r < BN; r += 32) {
            const float* src = (k0 < 1536)
                ? W1 + (size_t)(n0 + r) * 1536 + k0 + lk4
                : W2 + (size_t)(n0 + r) * Hq + (k0 - 1536) + lk4;
            float4 vv = *reinterpret_cast<const float4*>(src);
            float hx, lx, hy, ly, hz, lz, hw, lw;
            split_bf16(vv.x, hx, lx); split_bf16(vv.y, hy, ly);
            split_bf16(vv.z, hz, lz); split_bf16(vv.w, hw, lw);
            Ba[r][lp]     = make_uint2(pack2(hx, hy), pack2(lx, ly));
            Ba[r][lp + 1] = make_uint2(pack2(hz, hw), pack2(lz, lw));
        }
        __syncthreads();

#pragma unroll
        for (int kk = 0; kk < PP; kk += 8) {
            unsigned ah[MI][4], al[MI][4], bh[NI][2], bl[NI][2];
#pragma unroll
            for (int i = 0; i < MI; i++) {
                int r = warp_m + i * 16 + (lane >> 2);
                int cb = kk + (lane & 3);
                uint2 t0 = Aa[r][cb];      ah[i][0] = t0.x; al[i][0] = t0.y;
                uint2 t1 = Aa[r + 8][cb];  ah[i][1] = t1.x; al[i][1] = t1.y;
                uint2 t2 = Aa[r][cb + 4];  ah[i][2] = t2.x; al[i][2] = t2.y;
                uint2 t3 = Aa[r + 8][cb + 4]; ah[i][3] = t3.x; al[i][3] = t3.y;
            }
#pragma unroll
            for (int j = 0; j < NI; j++) {
                int r = warp_n + j * 8 + (lane >> 2);
                int cb = kk + (lane & 3);
                uint2 t0 = Ba[r][cb];      bh[j][0] = t0.x; bl[j][0] = t0.y;
                uint2 t1 = Ba[r][cb + 4];  bh[j][1] = t1.x; bl[j][1] = t1.y;
            }
#pragma unroll
            for (int i = 0; i < MI; i++)
#pragma unroll
                for (int j = 0; j < NI; j++) {
                    mma_bf16(acc[i][j], ah[i], bl[j]);
                    mma_bf16(acc[i][j], al[i], bh[j]);
                    mma_bf16(acc[i][j], ah[i], bh[j]);
                }
        }
        __syncthreads();
    }

#pragma unroll
    for (int i = 0; i < MI; i++)
#pragma unroll
        for (int j = 0; j < NI; j++) {
            int row = warp_m + i * 16 + (lane >> 2);
            int col = n0 + warp_n + j * 8 + 2 * (lane & 3);
#pragma unroll
            for (int q = 0; q < 4; q++) {
                int gr = row + (q >> 1) * 8;
                int gc = col + (q & 1);
                g_gates[(size_t)gr * G4q + gc] =
                    acc[i][j][q] + b1[gc] + b2[gc];
            }
        }
}

// ====== logits GEMM: single-pass bf16 m16n8k16 (proven) =====================
__global__ void __launch_bounds__(256)
logits_kernel(const float* __restrict__ A, const float* __restrict__ Bm,
              float* __restrict__ C, const float* __restrict__ bias)
{
    constexpr int BM = 64, BN = 128, BK = 32;
    constexpr int MI = 2, NI = 4;
    constexpr int PP = 16, KPP = 20;
    const int N = Vq, K = Hq;

    __shared__ unsigned Aa[BM][KPP];
    __shared__ unsigned Ba[BN][KPP];

    const int tid = threadIdx.x;
    const int lane = tid & 31;
    const int w = tid >> 5;
    const int warp_m = (w & 1) * 32;
    const int warp_n = (w >> 1) * 32;
    const int n0 = blockIdx.x * BN;
    const int lrow = tid >> 3;
    const int lk4 = (tid & 7) * 4;
    const int lp = lk4 >> 1;

    float acc[MI][NI][4];
#pragma unroll
    for (int i = 0; i < MI; i++)
#pragma unroll
        for (int j = 0; j < NI; j++)
#pragma unroll
            for (int q = 0; q < 4; q++) acc[i][j][q] = 0.f;

    for (int k0 = 0; k0 < K; k0 += BK) {
#pragma unroll
        for (int r = lrow; r < BM; r += 32) {
            float4 vv = *reinterpret_cast<const float4*>(
                A + (size_t)r * K + k0 + lk4);
            Aa[r][lp]     = pack2(vv.x, vv.y);
            Aa[r][lp + 1] = pack2(vv.z, vv.w);
        }
#pragma unroll
        for (int r = lrow; r < BN; r += 32) {
            float4 vv = make_float4(0.f, 0.f, 0.f, 0.f);
            if (n0 + r < N)
                vv = *reinterpret_cast<const float4*>(
                    Bm + (size_t)(n0 + r) * K + k0 + lk4);
            Ba[r][lp]     = pack2(vv.x, vv.y);
            Ba[r][lp + 1] = pack2(vv.z, vv.w);
        }
        __syncthreads();

#pragma unroll
        for (int kk = 0; kk < PP; kk += 8) {
            unsigned af[MI][4], bf[NI][2];
#pragma unroll
            for (int i = 0; i < MI; i++) {
                int r = warp_m + i * 16 + (lane >> 2);
                int cb = kk + (lane & 3);
                af[i][0] = Aa[r][cb];     af[i][1] = Aa[r + 8][cb];
                af[i][2] = Aa[r][cb + 4]; af[i][3] = Aa[r + 8][cb + 4];
            }
#pragma unroll
            for (int j = 0; j < NI; j++) {
                int r = warp_n + j * 8 + (lane >> 2);
                int cb = kk + (lane & 3);
                bf[j][0] = Ba[r][cb]; bf[j][1] = Ba[r][cb + 4];
            }
#pragma unroll
            for (int i = 0; i < MI; i++)
#pragma unroll
                for (int j = 0; j < NI; j++)
                    mma_bf16(acc[i][j], af[i], bf[j]);
        }
        __syncthreads();
    }

#pragma unroll
    for (int i = 0; i < MI; i++)
#pragma unroll
        for (int j = 0; j < NI; j++) {
            int row = warp_m + i * 16 + (lane >> 2);
            int col = n0 + warp_n + j * 8 + 2 * (lane & 3);
#pragma unroll
            for (int q = 0; q < 4; q++) {
                int gr = row + (q >> 1) * 8;
                int gc = col + (q & 1);
                if (gc < N)
                    C[(size_t)gr * N + gc] = acc[i][j][q] + bias[gc];
            }
        }
}

// ---------------- pointwise / reduction kernels -----------------------------
__global__ void softmax_kernel(float* __restrict__ attn_out)
{
    __shared__ float sm[Sq];
    int b = blockIdx.x, t = threadIdx.x;
    float x = 0.f;
#pragma unroll
    for (int q = 0; q < NSLOT; q++)
        x += g_spart[(size_t)q * SBq + t * Bq + b];
    sm[t] = x; __syncthreads();
    for (int o = 64; o > 0; o >>= 1) {
        if (t < o) sm[t] = fmaxf(sm[t], sm[t + o]);
        __syncthreads();
    }
    float m = sm[0];
    __syncthreads();
    float e = expf(x - m);
    sm[t] = e; __syncthreads();
    for (int o = 64; o > 0; o >>= 1) {
        if (t < o) sm[t] += sm[t + o];
        __syncthreads();
    }
    attn_out[b * Sq + t] = e / sm[0];
}

__global__ void context_kernel(const float* __restrict__ attn,
                               const float* __restrict__ enc)
{
    __shared__ float aw[Sq];
    int idx = blockIdx.x * 256 + threadIdx.x;
    int b = idx >> 10;
    int h = idx & (Hq - 1);
    if (threadIdx.x < Sq) aw[threadIdx.x] = attn[b * Sq + threadIdx.x];
    __syncthreads();
    float acc = 0.f;
#pragma unroll 8
    for (int s = 0; s < Sq; s++)
        acc = fmaf(aw[s], enc[((size_t)s * Bq + b) * Hq + h], acc);
    g_ctx[idx] = acc;
}

__global__ void xbuild_kernel(const int* __restrict__ seq,
                              const float* __restrict__ emb,
                              const float* __restrict__ h0)
{
    int idx = blockIdx.x * 256 + threadIdx.x;
    int b = idx / K2q;
    int j = idx - b * K2q;
    float val;
    if (j < Eq)            val = emb[(size_t)seq[b] * Eq + j];
    else if (j < Eq + Hq)  val = g_ctx[b * Hq + (j - Eq)];
    else                   val = h0[b * Hq + (j - Eq - Hq)];
    g_x2[idx] = val;
}

__device__ __forceinline__ float sigf(float x) { return 1.f / (1.f + expf(-x)); }

__global__ void lstm_kernel(const float* __restrict__ c0,
                            float* __restrict__ h_new,
                            float* __restrict__ c_new)
{
    int idx = blockIdx.x * 256 + threadIdx.x;
    int b = idx >> 10;
    int h = idx & (Hq - 1);
    const float* g = g_gates + ((size_t)b << 12);
    float vi = g[h];
    float vf = g[Hq + h];
    float vg = g[2 * Hq + h];
    float vo = g[3 * Hq + h];
    float c = sigf(vf) * c0[idx] + sigf(vi) * tanhf(vg);
    c_new[idx] = c;
    h_new[idx] = sigf(vo) * tanhf(c);
}

// ---- two-phase log-softmax -------------------------------------------------
__global__ void ls_partial_kernel(const float* __restrict__ out)
{
    __shared__ float red[8];
    int b = blockIdx.x, c = blockIdx.y, t = threadIdx.x;
    const float* row = out + (size_t)b * Vq;
    int j0 = c * LSC;
    int j1 = min(j0 + LSC, Vq);

    float m = -1e30f;
    for (int j = j0 + t; j < j1; j += 256) m = fmaxf(m, row[j]);
#pragma unroll
    for (int o = 16; o > 0; o >>= 1) m = fmaxf(m, __shfl_xor_sync(~0u, m, o));
    if ((t & 31) == 0) red[t >> 5] = m;
    __syncthreads();
    if (t < 32) {
        float vv = (t < 8) ? red[t] : -1e30f;
#pragma unroll
        for (int o = 4; o > 0; o >>= 1) vv = fmaxf(vv, __shfl_xor_sync(~0u, vv, o));
        if (t == 0) red[0] = vv;
    }
    __syncthreads();
    m = red[0];
    __syncthreads();

    float s = 0.f;
    for (int j = j0 + t; j < j1; j += 256) s += expf(row[j] - m);
#pragma unroll
    for (int o = 16; o > 0; o >>= 1) s += __shfl_xor_sync(~0u, s, o);
    if ((t & 31) == 0) red[t >> 5] = s;
    __syncthreads();
    if (t < 32) {
        float vv = (t < 8) ? red[t] : 0.f;
#pragma unroll
        for (int o = 4; o > 0; o >>= 1) vv += __shfl_xor_sync(~0u, vv, o);
        if (t == 0) {
            g_lsm[b * 8 + c] = m;
            g_lss[b * 8 + c] = vv;
        }
    }
}

__global__ void ls_apply_kernel(float* __restrict__ out)
{
    int b = blockIdx.x, c = blockIdx.y, t = threadIdx.x;
    float M = -1e30f;
#pragma unroll
    for (int q = 0; q < 8; q++) M = fmaxf(M, g_lsm[b * 8 + q]);
    float S = 0.f;
#pragma unroll
    for (int q = 0; q < 8; q++)
        S += g_lss[b * 8 + q] * expf(g_lsm[b * 8 + q] - M);
    float lse = M + logf(S);

    float* row = out + (size_t)b * Vq;
    int j0 = c * LSC;
    int j1 = min(j0 + LSC, Vq);
    for (int j = j0 + t; j < j1; j += 256) row[j] -= lse;
}

// ---------------------------------------------------------------------------
extern "C" void kernel_launch(void* const* d_in, const int* in_sizes, int n_in,
                              void* d_out, int out_size)
{
    const int*   seq     = (const int*)d_in[0];
    const float* h0      = (const float*)d_in[1];
    const float* c0      = (const float*)d_in[2];
    const float* enc     = (const float*)d_in[3];
    const float* emb     = (const float*)d_in[4];
    const float* W_ih    = (const float*)d_in[5];
    const float* W_hh    = (const float*)d_in[6];
    const float* b_ih    = (const float*)d_in[7];
    const float* b_hh    = (const float*)d_in[8];
    const float* attn_W  = (const float*)d_in[9];
    const float* attn_Wb = (const float*)d_in[10];
    const float* attn_U  = (const float*)d_in[11];
    const float* attn_Ub = (const float*)d_in[12];
    const float* attn_v  = (const float*)d_in[13];
    const float* out_W   = (const float*)d_in[14];
    const float* out_b   = (const float*)d_in[15];

    float* out      = (float*)d_out;
    float* o_logits = out;                          // [B, V]
    float* o_h      = out + (size_t)Bq * Vq;        // [1, B, H]
    float* o_c      = o_h + Bq * Hq;                // [1, B, H]
    float* o_attn   = o_c + Bq * Hq;                // [B, 1, S]

    float* hW;
    cudaGetSymbolAddress((void**)&hW, g_hW);

    cudaFuncSetAttribute(tgemm_score_kernel,
                         cudaFuncAttributeMaxDynamicSharedMemorySize, TS_SMEM);

    // 1) hW = h0 @ attn_W^T + attn_Wb            [64, 1024]  (3xBF16, 16 CTA)
    mma3bf_gemm_nt<64, 64, 32, 32, 16><<<dim3(Hq / 64, 1), 256>>>(
        h0, attn_W, hW, Bq, Hq, Hq, attn_Wb);

    // 2-3) pre-split enc and U to hi/lo bf16x2 pairs
    presplit_kernel_enc<<<SBq * Hq / 1024, 256>>>(enc);
    presplit_kernel_u<<<Hq * Hq / 1024, 256>>>(attn_U);

    // 4) T GEMM (pre-split, 4-stage cp.async, BK=16, immediate LDS) + score
    tgemm_score_kernel<<<dim3(Hq / 64, SBq / 128), 256, TS_SMEM>>>(
        attn_Ub, attn_v);

    // 5) attn = softmax(reduce(spart)) -> output region
    softmax_kernel<<<Bq, Sq>>>(o_attn);

    // 6) context = attn @ enc                    [64, 1024]
    context_kernel<<<Bq * Hq / 256, 256>>>(o_attn, enc);

    // 7) x2 = [emb[seq] ; ctx ; h0]              [64, 2560]
    xbuild_kernel<<<Bq * K2q / 256, 256>>>(seq, emb, h0);

    // 8) gates = x2 @ [W_ih;W_hh]^T + biases     (fused, 64 CTA)
    gates_kernel<<<dim3(G4q / 64, 1), 256>>>(W_ih, W_hh, b_ih, b_hh);

    // 9) LSTM pointwise -> h_new, c_new in output
    lstm_kernel<<<Bq * Hq / 256, 256>>>(c0, o_h, o_c);

    // 10) logits = h_new @ out_W^T + out_b       (single bf16)
    logits_kernel<<<dim3((Vq + 127) / 128, 1), 256>>>(
        o_h, out_W, o_logits, out_b);

    // 11-12) log_softmax: partials then apply
    ls_partial_kernel<<<dim3(Bq, 8), 256>>>(o_logits);
    ls_apply_kernel<<<dim3(Bq, 8), 256>>>(o_logits);
}

// round 16
// speedup vs baseline: 1.5761x; 1.5761x over previous
#include <cuda_runtime.h>
#include <cuda_bf16.h>
#include <math.h>
#include <stdint.h>

#define Bq 64
#define Sq 128
#define Eq 512
#define Hq 1024
#define Vq 50257
#define K2q 2560        /* E + H + H : fused gates K */
#define G4q (4 * Hq)
#define SBq (Sq * Bq)
#define NSLOT 32
#define LSC 6304

// ---------------- scratch (static device globals; no runtime allocation) ----
__device__ float g_hW[Bq * Hq];
__device__ float g_spart[NSLOT * SBq];
__device__ float g_ctx[Bq * Hq];
__device__ float g_x2[Bq * K2q];
__device__ float g_gates[Bq * G4q];
__device__ float g_lsm[Bq * 8];
__device__ float g_lss[Bq * 8];
__device__ uint2 g_es[SBq * 512];      // enc pre-split: hi/lo bf16x2 pairs
__device__ uint2 g_us[Hq * 512];       // U pre-split

// ---------------- helpers ---------------------------------------------------
__device__ __forceinline__ uint32_t smem_u32(const void* p)
{
    uint32_t a;
    asm("{ .reg .u64 t; cvta.to.shared.u64 t, %1; cvt.u32.u64 %0, t; }"
        : "=r"(a) : "l"(p));
    return a;
}

__device__ __forceinline__ void split_bf16(float x, float& hi, float& lo)
{
    hi = __bfloat162float(__float2bfloat16(x));
    lo = x - hi;
}

__device__ __forceinline__ unsigned pack2(float e0, float e1)
{
    unsigned r;
    asm("cvt.rn.bf16x2.f32 %0, %1, %2;" : "=r"(r) : "f"(e1), "f"(e0));
    return r;
}

__device__ __forceinline__ void mma_bf16(float c[4], const unsigned a[4],
                                         const unsigned b[2])
{
    asm volatile(
        "mma.sync.aligned.m16n8k16.row.col.f32.bf16.bf16.f32 "
        "{%0,%1,%2,%3}, {%4,%5,%6,%7}, {%8,%9}, {%0,%1,%2,%3};"
        : "+f"(c[0]), "+f"(c[1]), "+f"(c[2]), "+f"(c[3])
        : "r"(a[0]), "r"(a[1]), "r"(a[2]), "r"(a[3]), "r"(b[0]), "r"(b[1]));
}

__device__ __forceinline__ float tanh_fast(float x)
{
    float cx = fminf(fmaxf(x, -15.f), 15.f);
    float e = __expf(2.f * cx);
    return __fdividef(e - 1.f, e + 1.f);
}

__device__ __forceinline__ void cp16(uint32_t dst, const void* src)
{
    asm volatile("cp.async.cg.shared.global [%0], [%1], 16;"
                 :: "r"(dst), "l"(src) : "memory");
}
__device__ __forceinline__ void cp_commit()
{
    asm volatile("cp.async.commit_group;" ::: "memory");
}
template <int N>
__device__ __forceinline__ void cp_wait()
{
    asm volatile("cp.async.wait_group %0;" :: "n"(N) : "memory");
}

// ================== pre-split kernels: fp32 -> hi/lo bf16x2 uint2 ===========
__global__ void presplit_kernel_enc(const float* __restrict__ src)
{
    size_t i = (size_t)blockIdx.x * 256 + threadIdx.x;   // float4 index
    float4 v = reinterpret_cast<const float4*>(src)[i];
    float hx, lx, hy, ly, hz, lz, hw, lw;
    split_bf16(v.x, hx, lx); split_bf16(v.y, hy, ly);
    split_bf16(v.z, hz, lz); split_bf16(v.w, hw, lw);
    g_es[2 * i]     = make_uint2(pack2(hx, hy), pack2(lx, ly));
    g_es[2 * i + 1] = make_uint2(pack2(hz, hw), pack2(lz, lw));
}

__global__ void presplit_kernel_u(const float* __restrict__ src)
{
    size_t i = (size_t)blockIdx.x * 256 + threadIdx.x;
    float4 v = reinterpret_cast<const float4*>(src)[i];
    float hx, lx, hy, ly, hz, lz, hw, lw;
    split_bf16(v.x, hx, lx); split_bf16(v.y, hy, ly);
    split_bf16(v.z, hz, lz); split_bf16(v.w, hw, lw);
    g_us[2 * i]     = make_uint2(pack2(hx, hy), pack2(lx, ly));
    g_us[2 * i + 1] = make_uint2(pack2(hz, hw), pack2(lz, lw));
}

// ============ T GEMM: pre-split, 3-stage cp.async, ROWP=20, full unroll =====
// T = enc[8192,1024] @ U[1024,1024]^T; score partials out (32 slots).
// BM=128, BN=64, BK=32 (16 pairs/chunk, 32 chunks); warp grid 4(M)x2(N).
// ROWP=20 -> conflict-free LDS.64; full unroll folds stage offsets to imms.
#define TS_ROWP 20                      /* uint2 per row (16 data + 4 pad) */
#define TS_B (128 * TS_ROWP)            /* B offset in uint2 = 2560 */
#define TS_STG (192 * TS_ROWP)          /* uint2 per stage = 3840 */
#define TS_STGB (TS_STG * 8)            /* 30720 B */
#define TS_SMEM (3 * TS_STGB)           /* 92160 B */

__global__ void __launch_bounds__(256, 2)
tgemm_score_kernel(const float* __restrict__ Ub, const float* __restrict__ v)
{
    extern __shared__ uint2 smt[];
    constexpr int MI = 2, NI = 4;

    const int tid = threadIdx.x;
    const int lane = tid & 31;
    const int w = tid >> 5;
    const int lane4 = lane >> 2;
    const int lanek = lane & 3;
    const int warp_m = (w & 3) * 32;
    const int warp_n = (w >> 2) * 32;
    const int m0 = blockIdx.y * 128;
    const int n0 = blockIdx.x * 64;

    // ---- hoisted loader addressing (computed once) -------------------------
    const uint32_t sb0 = smem_u32(smt);
    uint32_t adst[4], bdst[2];
    const uint2* asrc[4];
    const uint2* bsrc[2];
#pragma unroll
    for (int u = 0; u < 4; u++) {
        int i = tid + 256 * u;
        int row = i >> 3, pe = (i & 7) * 2;
        adst[u] = (uint32_t)(row * TS_ROWP + pe) * 8;
        asrc[u] = g_es + (size_t)(m0 + row) * 512 + pe;
    }
#pragma unroll
    for (int u = 0; u < 2; u++) {
        int i = tid + 256 * u;
        int row = i >> 3, pe = (i & 7) * 2;
        bdst[u] = (uint32_t)(TS_B + row * TS_ROWP + pe) * 8;
        bsrc[u] = g_us + (size_t)(n0 + row) * 512 + pe;
    }

    float acc[MI][NI][4];
#pragma unroll
    for (int i = 0; i < MI; i++)
#pragma unroll
        for (int j = 0; j < NI; j++)
#pragma unroll
            for (int q = 0; q < 4; q++) acc[i][j][q] = 0.f;

    auto issue = [&](int ch) {
        // ch is a compile-time literal at every call site (full unroll)
        uint32_t base = sb0 + (uint32_t)(ch % 3) * TS_STGB;
        int ko = ch * 16;
#pragma unroll
        for (int u = 0; u < 4; u++) cp16(base + adst[u], asrc[u] + ko);
#pragma unroll
        for (int u = 0; u < 2; u++) cp16(base + bdst[u], bsrc[u] + ko);
        cp_commit();
    };

    issue(0); issue(1);

    const int abase = (warp_m + lane4) * TS_ROWP + lanek;
    const int bbase = TS_B + (warp_n + lane4) * TS_ROWP + lanek;

#pragma unroll
    for (int ch = 0; ch < 32; ch++) {
        cp_wait<1>();
        __syncthreads();
        const uint2* pa = smt + (ch % 3) * TS_STG + abase;
        const uint2* pb = smt + (ch % 3) * TS_STG + bbase;

#pragma unroll
        for (int kk = 0; kk < 16; kk += 8) {
            unsigned ah[MI][4], al[MI][4], bh[NI][2], bl[NI][2];
#pragma unroll
            for (int i = 0; i < MI; i++) {
                uint2 t0 = pa[i * 320 + kk];         // +i*16 rows
                uint2 t1 = pa[i * 320 + 160 + kk];   // +8 rows
                uint2 t2 = pa[i * 320 + kk + 4];     // k+8 half
                uint2 t3 = pa[i * 320 + 160 + kk + 4];
                ah[i][0] = t0.x; al[i][0] = t0.y;
                ah[i][1] = t1.x; al[i][1] = t1.y;
                ah[i][2] = t2.x; al[i][2] = t2.y;
                ah[i][3] = t3.x; al[i][3] = t3.y;
            }
#pragma unroll
            for (int j = 0; j < NI; j++) {
                uint2 t0 = pb[j * 160 + kk];         // +j*8 rows
                uint2 t1 = pb[j * 160 + kk + 4];
                bh[j][0] = t0.x; bl[j][0] = t0.y;
                bh[j][1] = t1.x; bl[j][1] = t1.y;
            }
#pragma unroll
            for (int i = 0; i < MI; i++)
#pragma unroll
                for (int j = 0; j < NI; j++) {
                    mma_bf16(acc[i][j], ah[i], bl[j]);
                    mma_bf16(acc[i][j], al[i], bh[j]);
                    mma_bf16(acc[i][j], ah[i], bh[j]);
                }
        }

        if (ch + 2 < 32) issue(ch + 2);
        else cp_commit();               // keep group count consistent
        __syncthreads();
    }

    // ---- fused score epilogue over this warp's 32 columns ------------------
    float vv[NI][2], uu[NI][2];
#pragma unroll
    for (int j = 0; j < NI; j++)
#pragma unroll
        for (int qc = 0; qc < 2; qc++) {
            int c = n0 + warp_n + j * 8 + 2 * lanek + qc;
            vv[j][qc] = v[c];
            uu[j][qc] = Ub[c];
        }

    const int slot = blockIdx.x * 2 + (w >> 2);
#pragma unroll
    for (int i = 0; i < MI; i++)
#pragma unroll
        for (int qr = 0; qr < 2; qr++) {
            int row = m0 + warp_m + i * 16 + lane4 + qr * 8;
            int b = row & (Bq - 1);
            const float* hwr = g_hW + (size_t)b * Hq + n0 + warp_n + 2 * lanek;
            float part = 0.f;
#pragma unroll
            for (int j = 0; j < NI; j++)
#pragma unroll
                for (int qc = 0; qc < 2; qc++) {
                    float t = acc[i][j][2 * qr + qc] + uu[j][qc]
                              + hwr[j * 8 + qc];
                    part += vv[j][qc] * tanh_fast(t);
                }
            part += __shfl_xor_sync(0xffffffffu, part, 1);
            part += __shfl_xor_sync(0xffffffffu, part, 2);
            if (lanek == 0)
                g_spart[(size_t)slot * SBq + row] = part;
        }
}

// ================== 3xBF16 GEMM template (hW) ===============================
template <int BM, int BN, int BK, int WM, int WN>
__global__ void __launch_bounds__(256)
mma3bf_gemm_nt(const float* __restrict__ A, const float* __restrict__ Bm,
               float* __restrict__ C, int M, int N, int K,
               const float* __restrict__ bias)
{
    constexpr int MI = WM / 16;
    constexpr int NI = WN / 8;
    constexpr int PP = BK / 2;
    constexpr int KPP = PP + 4;
    constexpr int F4R = BK / 4;
    constexpr int RPP = 256 / F4R;

    __shared__ uint2 Aa[BM][KPP];
    __shared__ uint2 Ba[BN][KPP];

    const int tid = threadIdx.x;
    const int lane = tid & 31;
    const int w = tid >> 5;
    const int warp_m = (w % (BM / WM)) * WM;
    const int warp_n = (w / (BM / WM)) * WN;
    const int m0 = blockIdx.y * BM;
    const int n0 = blockIdx.x * BN;
    const int lrow = tid / F4R;
    const int lk4 = (tid % F4R) * 4;
    const int lp = lk4 >> 1;

    float acc[MI][NI][4];
#pragma unroll
    for (int i = 0; i < MI; i++)
#pragma unroll
        for (int j = 0; j < NI; j++)
#pragma unroll
            for (int q = 0; q < 4; q++) acc[i][j][q] = 0.f;

    for (int k0 = 0; k0 < K; k0 += BK) {
#pragma unroll
        for (int r = lrow; r < BM; r += RPP) {
            float4 vv = *reinterpret_cast<const float4*>(
                A + (size_t)(m0 + r) * K + k0 + lk4);
            float hx, lx, hy, ly, hz, lz, hw, lw;
            split_bf16(vv.x, hx, lx); split_bf16(vv.y, hy, ly);
            split_bf16(vv.z, hz, lz); split_bf16(vv.w, hw, lw);
            Aa[r][lp]     = make_uint2(pack2(hx, hy), pack2(lx, ly));
            Aa[r][lp + 1] = make_uint2(pack2(hz, hw), pack2(lz, lw));
        }
#pragma unroll
        for (int r = lrow; r < BN; r += RPP) {
            float4 vv = make_float4(0.f, 0.f, 0.f, 0.f);
            if (n0 + r < N)
                vv = *reinterpret_cast<const float4*>(
                    Bm + (size_t)(n0 + r) * K + k0 + lk4);
            float hx, lx, hy, ly, hz, lz, hw, lw;
            split_bf16(vv.x, hx, lx); split_bf16(vv.y, hy, ly);
            split_bf16(vv.z, hz, lz); split_bf16(vv.w, hw, lw);
            Ba[r][lp]     = make_uint2(pack2(hx, hy), pack2(lx, ly));
            Ba[r][lp + 1] = make_uint2(pack2(hz, hw), pack2(lz, lw));
        }
        __syncthreads();

#pragma unroll
        for (int kk = 0; kk < PP; kk += 8) {
            unsigned ah[MI][4], al[MI][4], bh[NI][2], bl[NI][2];
#pragma unroll
            for (int i = 0; i < MI; i++) {
                int r = warp_m + i * 16 + (lane >> 2);
                int cb = kk + (lane & 3);
                uint2 t0 = Aa[r][cb];      ah[i][0] = t0.x; al[i][0] = t0.y;
                uint2 t1 = Aa[r + 8][cb];  ah[i][1] = t1.x; al[i][1] = t1.y;
                uint2 t2 = Aa[r][cb + 4];  ah[i][2] = t2.x; al[i][2] = t2.y;
                uint2 t3 = Aa[r + 8][cb + 4]; ah[i][3] = t3.x; al[i][3] = t3.y;
            }
#pragma unroll
            for (int j = 0; j < NI; j++) {
                int r = warp_n + j * 8 + (lane >> 2);
                int cb = kk + (lane & 3);
                uint2 t0 = Ba[r][cb];      bh[j][0] = t0.x; bl[j][0] = t0.y;
                uint2 t1 = Ba[r][cb + 4];  bh[j][1] = t1.x; bl[j][1] = t1.y;
            }
#pragma unroll
            for (int i = 0; i < MI; i++)
#pragma unroll
                for (int j = 0; j < NI; j++) {
                    mma_bf16(acc[i][j], ah[i], bl[j]);
                    mma_bf16(acc[i][j], al[i], bh[j]);
                    mma_bf16(acc[i][j], ah[i], bh[j]);
                }
        }
        __syncthreads();
    }

#pragma unroll
    for (int i = 0; i < MI; i++)
#pragma unroll
        for (int j = 0; j < NI; j++) {
            int row = m0 + warp_m + i * 16 + (lane >> 2);
            int col = n0 + warp_n + j * 8 + 2 * (lane & 3);
#pragma unroll
            for (int q = 0; q < 4; q++) {
                int gr = row + (q >> 1) * 8;
                int gc = col + (q & 1);
                if (gc < N) {
                    float r = acc[i][j][q];
                    if (bias) r += bias[gc];
                    C[(size_t)gr * N + gc] = r;
                }
            }
        }
}

// ============ fused gates GEMM: [x2] @ [W_ih;W_hh]^T, K=2560, 3xBF16 ========
__global__ void __launch_bounds__(256)
gates_kernel(const float* __restrict__ W1, const float* __restrict__ W2,
             const float* __restrict__ b1, const float* __restrict__ b2)
{
    constexpr int BM = 64, BN = 64, BK = 32;
    constexpr int MI = 2, NI = 2;
    constexpr int PP = 16, KPP = 20;

    __shared__ uint2 Aa[BM][KPP];
    __shared__ uint2 Ba[BN][KPP];

    const int tid = threadIdx.x;
    const int lane = tid & 31;
    const int w = tid >> 5;
    const int warp_m = (w % 2) * 32;
    const int warp_n = (w / 2) * 16;
    const int n0 = blockIdx.x * BN;
    const int lrow = tid >> 3;
    const int lk4 = (tid & 7) * 4;
    const int lp = lk4 >> 1;

    float acc[MI][NI][4];
#pragma unroll
    for (int i = 0; i < MI; i++)
#pragma unroll
        for (int j = 0; j < NI; j++)
#pragma unroll
            for (int q = 0; q < 4; q++) acc[i][j][q] = 0.f;

    for (int k0 = 0; k0 < K2q; k0 += BK) {
#pragma unroll
        for (int r = lrow; r < BM; r += 32) {
            float4 vv = *reinterpret_cast<const float4*>(
                g_x2 + (size_t)r * K2q + k0 + lk4);
            float hx, lx, hy, ly, hz, lz, hw, lw;
            split_bf16(vv.x, hx, lx); split_bf16(vv.y, hy, ly);
            split_bf16(vv.z, hz, lz); split_bf16(vv.w, hw, lw);
            Aa[r][lp]     = make_uint2(pack2(hx, hy), pack2(lx, ly));
            Aa[r][lp + 1] = make_uint2(pack2(hz, hw), pack2(lz, lw));
        }
#pragma unroll
        for (int r = lrow; r < BN; r += 32) {
            const float* src = (k0 < 1536)
                ? W1 + (size_t)(n0 + r) * 1536 + k0 + lk4
                : W2 + (size_t)(n0 + r) * Hq + (k0 - 1536) + lk4;
            float4 vv = *reinterpret_cast<const float4*>(src);
            float hx, lx, hy, ly, hz, lz, hw, lw;
            split_bf16(vv.x, hx, lx); split_bf16(vv.y, hy, ly);
            split_bf16(vv.z, hz, lz); split_bf16(vv.w, hw, lw);
            Ba[r][lp]     = make_uint2(pack2(hx, hy), pack2(lx, ly));
            Ba[r][lp + 1] = make_uint2(pack2(hz, hw), pack2(lz, lw));
        }
        __syncthreads();

#pragma unroll
        for (int kk = 0; kk < PP; kk += 8) {
            unsigned ah[MI][4], al[MI][4], bh[NI][2], bl[NI][2];
#pragma unroll
            for (int i = 0; i < MI; i++) {
                int r = warp_m + i * 16 + (lane >> 2);
                int cb = kk + (lane & 3);
                uint2 t0 = Aa[r][cb];      ah[i][0] = t0.x; al[i][0] = t0.y;
                uint2 t1 = Aa[r + 8][cb];  ah[i][1] = t1.x; al[i][1] = t1.y;
                uint2 t2 = Aa[r][cb + 4];  ah[i][2] = t2.x; al[i][2] = t2.y;
                uint2 t3 = Aa[r + 8][cb + 4]; ah[i][3] = t3.x; al[i][3] = t3.y;
            }
#pragma unroll
            for (int j = 0; j < NI; j++) {
                int r = warp_n + j * 8 + (lane >> 2);
                int cb = kk + (lane & 3);
                uint2 t0 = Ba[r][cb];      bh[j][0] = t0.x; bl[j][0] = t0.y;
                uint2 t1 = Ba[r][cb + 4];  bh[j][1] = t1.x; bl[j][1] = t1.y;
            }
#pragma unroll
            for (int i = 0; i < MI; i++)
#pragma unroll
                for (int j = 0; j < NI; j++) {
                    mma_bf16(acc[i][j], ah[i], bl[j]);
                    mma_bf16(acc[i][j], al[i], bh[j]);
                    mma_bf16(acc[i][j], ah[i], bh[j]);
                }
        }
        __syncthreads();
    }

#pragma unroll
    for (int i = 0; i < MI; i++)
#pragma unroll
        for (int j = 0; j < NI; j++) {
            int row = warp_m + i * 16 + (lane >> 2);
            int col = n0 + warp_n + j * 8 + 2 * (lane & 3);
#pragma unroll
            for (int q = 0; q < 4; q++) {
                int gr = row + (q >> 1) * 8;
                int gc = col + (q & 1);
                g_gates[(size_t)gr * G4q + gc] =
                    acc[i][j][q] + b1[gc] + b2[gc];
            }
        }
}

// ====== logits GEMM: single-pass bf16 m16n8k16 (proven) =====================
__global__ void __launch_bounds__(256)
logits_kernel(const float* __restrict__ A, const float* __restrict__ Bm,
              float* __restrict__ C, const float* __restrict__ bias)
{
    constexpr int BM = 64, BN = 128, BK = 32;
    constexpr int MI = 2, NI = 4;
    constexpr int PP = 16, KPP = 20;
    const int N = Vq, K = Hq;

    __shared__ unsigned Aa[BM][KPP];
    __shared__ unsigned Ba[BN][KPP];

    const int tid = threadIdx.x;
    const int lane = tid & 31;
    const int w = tid >> 5;
    const int warp_m = (w & 1) * 32;
    const int warp_n = (w >> 1) * 32;
    const int n0 = blockIdx.x * BN;
    const int lrow = tid >> 3;
    const int lk4 = (tid & 7) * 4;
    const int lp = lk4 >> 1;

    float acc[MI][NI][4];
#pragma unroll
    for (int i = 0; i < MI; i++)
#pragma unroll
        for (int j = 0; j < NI; j++)
#pragma unroll
            for (int q = 0; q < 4; q++) acc[i][j][q] = 0.f;

    for (int k0 = 0; k0 < K; k0 += BK) {
#pragma unroll
        for (int r = lrow; r < BM; r += 32) {
            float4 vv = *reinterpret_cast<const float4*>(
                A + (size_t)r * K + k0 + lk4);
            Aa[r][lp]     = pack2(vv.x, vv.y);
            Aa[r][lp + 1] = pack2(vv.z, vv.w);
        }
#pragma unroll
        for (int r = lrow; r < BN; r += 32) {
            float4 vv = make_float4(0.f, 0.f, 0.f, 0.f);
            if (n0 + r < N)
                vv = *reinterpret_cast<const float4*>(
                    Bm + (size_t)(n0 + r) * K + k0 + lk4);
            Ba[r][lp]     = pack2(vv.x, vv.y);
            Ba[r][lp + 1] = pack2(vv.z, vv.w);
        }
        __syncthreads();

#pragma unroll
        for (int kk = 0; kk < PP; kk += 8) {
            unsigned af[MI][4], bf[NI][2];
#pragma unroll
            for (int i = 0; i < MI; i++) {
                int r = warp_m + i * 16 + (lane >> 2);
                int cb = kk + (lane & 3);
                af[i][0] = Aa[r][cb];     af[i][1] = Aa[r + 8][cb];
                af[i][2] = Aa[r][cb + 4]; af[i][3] = Aa[r + 8][cb + 4];
            }
#pragma unroll
            for (int j = 0; j < NI; j++) {
                int r = warp_n + j * 8 + (lane >> 2);
                int cb = kk + (lane & 3);
                bf[j][0] = Ba[r][cb]; bf[j][1] = Ba[r][cb + 4];
            }
#pragma unroll
            for (int i = 0; i < MI; i++)
#pragma unroll
                for (int j = 0; j < NI; j++)
                    mma_bf16(acc[i][j], af[i], bf[j]);
        }
        __syncthreads();
    }

#pragma unroll
    for (int i = 0; i < MI; i++)
#pragma unroll
        for (int j = 0; j < NI; j++) {
            int row = warp_m + i * 16 + (lane >> 2);
            int col = n0 + warp_n + j * 8 + 2 * (lane & 3);
#pragma unroll
            for (int q = 0; q < 4; q++) {
                int gr = row + (q >> 1) * 8;
                int gc = col + (q & 1);
                if (gc < N)
                    C[(size_t)gr * N + gc] = acc[i][j][q] + bias[gc];
            }
        }
}

// ---------------- pointwise / reduction kernels -----------------------------
__global__ void softmax_kernel(float* __restrict__ attn_out)
{
    __shared__ float sm[Sq];
    int b = blockIdx.x, t = threadIdx.x;
    float x = 0.f;
#pragma unroll
    for (int q = 0; q < NSLOT; q++)
        x += g_spart[(size_t)q * SBq + t * Bq + b];
    sm[t] = x; __syncthreads();
    for (int o = 64; o > 0; o >>= 1) {
        if (t < o) sm[t] = fmaxf(sm[t], sm[t + o]);
        __syncthreads();
    }
    float m = sm[0];
    __syncthreads();
    float e = expf(x - m);
    sm[t] = e; __syncthreads();
    for (int o = 64; o > 0; o >>= 1) {
        if (t < o) sm[t] += sm[t + o];
        __syncthreads();
    }
    attn_out[b * Sq + t] = e / sm[0];
}

__global__ void context_kernel(const float* __restrict__ attn,
                               const float* __restrict__ enc)
{
    __shared__ float aw[Sq];
    int idx = blockIdx.x * 256 + threadIdx.x;
    int b = idx >> 10;
    int h = idx & (Hq - 1);
    if (threadIdx.x < Sq) aw[threadIdx.x] = attn[b * Sq + threadIdx.x];
    __syncthreads();
    float acc = 0.f;
#pragma unroll 8
    for (int s = 0; s < Sq; s++)
        acc = fmaf(aw[s], enc[((size_t)s * Bq + b) * Hq + h], acc);
    g_ctx[idx] = acc;
}

__global__ void xbuild_kernel(const int* __restrict__ seq,
                              const float* __restrict__ emb,
                              const float* __restrict__ h0)
{
    int idx = blockIdx.x * 256 + threadIdx.x;
    int b = idx / K2q;
    int j = idx - b * K2q;
    float val;
    if (j < Eq)            val = emb[(size_t)seq[b] * Eq + j];
    else if (j < Eq + Hq)  val = g_ctx[b * Hq + (j - Eq)];
    else                   val = h0[b * Hq + (j - Eq - Hq)];
    g_x2[idx] = val;
}

__device__ __forceinline__ float sigf(float x) { return 1.f / (1.f + expf(-x)); }

__global__ void lstm_kernel(const float* __restrict__ c0,
                            float* __restrict__ h_new,
                            float* __restrict__ c_new)
{
    int idx = blockIdx.x * 256 + threadIdx.x;
    int b = idx >> 10;
    int h = idx & (Hq - 1);
    const float* g = g_gates + ((size_t)b << 12);
    float vi = g[h];
    float vf = g[Hq + h];
    float vg = g[2 * Hq + h];
    float vo = g[3 * Hq + h];
    float c = sigf(vf) * c0[idx] + sigf(vi) * tanhf(vg);
    c_new[idx] = c;
    h_new[idx] = sigf(vo) * tanhf(c);
}

// ---- two-phase log-softmax -------------------------------------------------
__global__ void ls_partial_kernel(const float* __restrict__ out)
{
    __shared__ float red[8];
    int b = blockIdx.x, c = blockIdx.y, t = threadIdx.x;
    const float* row = out + (size_t)b * Vq;
    int j0 = c * LSC;
    int j1 = min(j0 + LSC, Vq);

    float m = -1e30f;
    for (int j = j0 + t; j < j1; j += 256) m = fmaxf(m, row[j]);
#pragma unroll
    for (int o = 16; o > 0; o >>= 1) m = fmaxf(m, __shfl_xor_sync(~0u, m, o));
    if ((t & 31) == 0) red[t >> 5] = m;
    __syncthreads();
    if (t < 32) {
        float vv = (t < 8) ? red[t] : -1e30f;
#pragma unroll
        for (int o = 4; o > 0; o >>= 1) vv = fmaxf(vv, __shfl_xor_sync(~0u, vv, o));
        if (t == 0) red[0] = vv;
    }
    __syncthreads();
    m = red[0];
    __syncthreads();

    float s = 0.f;
    for (int j = j0 + t; j < j1; j += 256) s += expf(row[j] - m);
#pragma unroll
    for (int o = 16; o > 0; o >>= 1) s += __shfl_xor_sync(~0u, s, o);
    if ((t & 31) == 0) red[t >> 5] = s;
    __syncthreads();
    if (t < 32) {
        float vv = (t < 8) ? red[t] : 0.f;
#pragma unroll
        for (int o = 4; o > 0; o >>= 1) vv += __shfl_xor_sync(~0u, vv, o);
        if (t == 0) {
            g_lsm[b * 8 + c] = m;
            g_lss[b * 8 + c] = vv;
        }
    }
}

__global__ void ls_apply_kernel(float* __restrict__ out)
{
    int b = blockIdx.x, c = blockIdx.y, t = threadIdx.x;
    float M = -1e30f;
#pragma unroll
    for (int q = 0; q < 8; q++) M = fmaxf(M, g_lsm[b * 8 + q]);
    float S = 0.f;
#pragma unroll
    for (int q = 0; q < 8; q++)
        S += g_lss[b * 8 + q] * expf(g_lsm[b * 8 + q] - M);
    float lse = M + logf(S);

    float* row = out + (size_t)b * Vq;
    int j0 = c * LSC;
    int j1 = min(j0 + LSC, Vq);
    for (int j = j0 + t; j < j1; j += 256) row[j] -= lse;
}

// ---------------------------------------------------------------------------
extern "C" void kernel_launch(void* const* d_in, const int* in_sizes, int n_in,
                              void* d_out, int out_size)
{
    const int*   seq     = (const int*)d_in[0];
    const float* h0      = (const float*)d_in[1];
    const float* c0      = (const float*)d_in[2];
    const float* enc     = (const float*)d_in[3];
    const float* emb     = (const float*)d_in[4];
    const float* W_ih    = (const float*)d_in[5];
    const float* W_hh    = (const float*)d_in[6];
    const float* b_ih    = (const float*)d_in[7];
    const float* b_hh    = (const float*)d_in[8];
    const float* attn_W  = (const float*)d_in[9];
    const float* attn_Wb = (const float*)d_in[10];
    const float* attn_U  = (const float*)d_in[11];
    const float* attn_Ub = (const float*)d_in[12];
    const float* attn_v  = (const float*)d_in[13];
    const float* out_W   = (const float*)d_in[14];
    const float* out_b   = (const float*)d_in[15];

    float* out      = (float*)d_out;
    float* o_logits = out;                          // [B, V]
    float* o_h      = out + (size_t)Bq * Vq;        // [1, B, H]
    float* o_c      = o_h + Bq * Hq;                // [1, B, H]
    float* o_attn   = o_c + Bq * Hq;                // [B, 1, S]

    float* hW;
    cudaGetSymbolAddress((void**)&hW, g_hW);

    cudaFuncSetAttribute(tgemm_score_kernel,
                         cudaFuncAttributeMaxDynamicSharedMemorySize, TS_SMEM);

    // 1) hW = h0 @ attn_W^T + attn_Wb            [64, 1024]  (3xBF16, 16 CTA)
    mma3bf_gemm_nt<64, 64, 32, 32, 16><<<dim3(Hq / 64, 1), 256>>>(
        h0, attn_W, hW, Bq, Hq, Hq, attn_Wb);

    // 2-3) pre-split enc and U to hi/lo bf16x2 pairs
    presplit_kernel_enc<<<SBq * Hq / 1024, 256>>>(enc);
    presplit_kernel_u<<<Hq * Hq / 1024, 256>>>(attn_U);

    // 4) T GEMM (pre-split, 3-stage cp.async, conflict-free, unrolled) + score
    tgemm_score_kernel<<<dim3(Hq / 64, SBq / 128), 256, TS_SMEM>>>(
        attn_Ub, attn_v);

    // 5) attn = softmax(reduce(spart)) -> output region
    softmax_kernel<<<Bq, Sq>>>(o_attn);

    // 6) context = attn @ enc                    [64, 1024]
    context_kernel<<<Bq * Hq / 256, 256>>>(o_attn, enc);

    // 7) x2 = [emb[seq] ; ctx ; h0]              [64, 2560]
    xbuild_kernel<<<Bq * K2q / 256, 256>>>(seq, emb, h0);

    // 8) gates = x2 @ [W_ih;W_hh]^T + biases     (fused, 64 CTA)
    gates_kernel<<<dim3(G4q / 64, 1), 256>>>(W_ih, W_hh, b_ih, b_hh);

    // 9) LSTM pointwise -> h_new, c_new in output
    lstm_kernel<<<Bq * Hq / 256, 256>>>(c0, o_h, o_c);

    // 10) logits = h_new @ out_W^T + out_b       (single bf16)
    logits_kernel<<<dim3((Vq + 127) / 128, 1), 256>>>(
        o_h, out_W, o_logits, out_b);

    // 11-12) log_softmax: partials then apply
    ls_partial_kernel<<<dim3(Bq, 8), 256>>>(o_logits);
    ls_apply_kernel<<<dim3(Bq, 8), 256>>>(o_logits);
}

// round 17
// speedup vs baseline: 1.6210x; 1.0285x over previous
#include <cuda_runtime.h>
#include <cuda_bf16.h>
#include <math.h>
#include <stdint.h>

#define Bq 64
#define Sq 128
#define Eq 512
#define Hq 1024
#define Vq 50257
#define K2q 2560        /* E + H + H : fused gates K */
#define G4q (4 * Hq)
#define SBq (Sq * Bq)
#define NSLOT 32
#define LSC 6304
#define ENC4 (SBq * Hq / 4)   /* enc float4 count */

// ---------------- scratch (static device globals; no runtime allocation) ----
__device__ float g_hW[Bq * Hq];
__device__ float g_spart[NSLOT * SBq];
__device__ float g_ctx[Bq * Hq];
__device__ float g_x2[Bq * K2q];
__device__ float g_gates[Bq * G4q];
__device__ float g_lsm[Bq * 8];
__device__ float g_lss[Bq * 8];
__device__ uint2 g_es[SBq * 512];      // enc pre-split: hi/lo bf16x2 pairs
__device__ uint2 g_us[Hq * 512];       // U pre-split

// ---------------- helpers ---------------------------------------------------
__device__ __forceinline__ uint32_t smem_u32(const void* p)
{
    uint32_t a;
    asm("{ .reg .u64 t; cvta.to.shared.u64 t, %1; cvt.u32.u64 %0, t; }"
        : "=r"(a) : "l"(p));
    return a;
}

__device__ __forceinline__ void split_bf16(float x, float& hi, float& lo)
{
    hi = __bfloat162float(__float2bfloat16(x));
    lo = x - hi;
}

__device__ __forceinline__ unsigned pack2(float e0, float e1)
{
    unsigned r;
    asm("cvt.rn.bf16x2.f32 %0, %1, %2;" : "=r"(r) : "f"(e1), "f"(e0));
    return r;
}

__device__ __forceinline__ void mma_bf16(float c[4], const unsigned a[4],
                                         const unsigned b[2])
{
    asm volatile(
        "mma.sync.aligned.m16n8k16.row.col.f32.bf16.bf16.f32 "
        "{%0,%1,%2,%3}, {%4,%5,%6,%7}, {%8,%9}, {%0,%1,%2,%3};"
        : "+f"(c[0]), "+f"(c[1]), "+f"(c[2]), "+f"(c[3])
        : "r"(a[0]), "r"(a[1]), "r"(a[2]), "r"(a[3]), "r"(b[0]), "r"(b[1]));
}

__device__ __forceinline__ float tanh_fast(float x)
{
    float cx = fminf(fmaxf(x, -15.f), 15.f);
    float e = __expf(2.f * cx);
    return __fdividef(e - 1.f, e + 1.f);
}

__device__ __forceinline__ void cp16(uint32_t dst, const void* src)
{
    asm volatile("cp.async.cg.shared.global [%0], [%1], 16;"
                 :: "r"(dst), "l"(src) : "memory");
}
__device__ __forceinline__ void cp16g(uint32_t dst, const void* src, int ok)
{
    asm volatile("cp.async.cg.shared.global [%0], [%1], 16, %2;"
                 :: "r"(dst), "l"(src), "r"(ok ? 16 : 0) : "memory");
}
__device__ __forceinline__ void cp_commit()
{
    asm volatile("cp.async.commit_group;" ::: "memory");
}
template <int N>
__device__ __forceinline__ void cp_wait()
{
    asm volatile("cp.async.wait_group %0;" :: "n"(N) : "memory");
}

// ================== merged pre-split kernel: fp32 -> hi/lo uint2 ============
__global__ void presplit_kernel(const float* __restrict__ enc,
                                const float* __restrict__ U)
{
    size_t i = (size_t)blockIdx.x * 256 + threadIdx.x;   // float4 index
    const float4* src4;
    uint2* dst;
    if (i < ENC4) {
        src4 = reinterpret_cast<const float4*>(enc) + i;
        dst = g_es + 2 * i;
    } else {
        size_t j = i - ENC4;
        src4 = reinterpret_cast<const float4*>(U) + j;
        dst = g_us + 2 * j;
    }
    float4 v = *src4;
    float hx, lx, hy, ly, hz, lz, hw, lw;
    split_bf16(v.x, hx, lx); split_bf16(v.y, hy, ly);
    split_bf16(v.z, hz, lz); split_bf16(v.w, hw, lw);
    dst[0] = make_uint2(pack2(hx, hy), pack2(lx, ly));
    dst[1] = make_uint2(pack2(hz, hw), pack2(lz, lw));
}

// ============ T GEMM: pre-split, 3-stage cp.async, ROWP=20, full unroll =====
#define TS_ROWP 20                      /* uint2 per row (16 data + 4 pad) */
#define TS_B (128 * TS_ROWP)            /* B offset in uint2 = 2560 */
#define TS_STG (192 * TS_ROWP)          /* uint2 per stage = 3840 */
#define TS_STGB (TS_STG * 8)            /* 30720 B */
#define TS_SMEM (3 * TS_STGB)           /* 92160 B */

__global__ void __launch_bounds__(256, 2)
tgemm_score_kernel(const float* __restrict__ Ub, const float* __restrict__ v)
{
    extern __shared__ uint2 smt[];
    constexpr int MI = 2, NI = 4;

    const int tid = threadIdx.x;
    const int lane = tid & 31;
    const int w = tid >> 5;
    const int lane4 = lane >> 2;
    const int lanek = lane & 3;
    const int warp_m = (w & 3) * 32;
    const int warp_n = (w >> 2) * 32;
    const int m0 = blockIdx.y * 128;
    const int n0 = blockIdx.x * 64;

    const uint32_t sb0 = smem_u32(smt);
    uint32_t adst[4], bdst[2];
    const uint2* asrc[4];
    const uint2* bsrc[2];
#pragma unroll
    for (int u = 0; u < 4; u++) {
        int i = tid + 256 * u;
        int row = i >> 3, pe = (i & 7) * 2;
        adst[u] = (uint32_t)(row * TS_ROWP + pe) * 8;
        asrc[u] = g_es + (size_t)(m0 + row) * 512 + pe;
    }
#pragma unroll
    for (int u = 0; u < 2; u++) {
        int i = tid + 256 * u;
        int row = i >> 3, pe = (i & 7) * 2;
        bdst[u] = (uint32_t)(TS_B + row * TS_ROWP + pe) * 8;
        bsrc[u] = g_us + (size_t)(n0 + row) * 512 + pe;
    }

    float acc[MI][NI][4];
#pragma unroll
    for (int i = 0; i < MI; i++)
#pragma unroll
        for (int j = 0; j < NI; j++)
#pragma unroll
            for (int q = 0; q < 4; q++) acc[i][j][q] = 0.f;

    auto issue = [&](int ch) {
        uint32_t base = sb0 + (uint32_t)(ch % 3) * TS_STGB;
        int ko = ch * 16;
#pragma unroll
        for (int u = 0; u < 4; u++) cp16(base + adst[u], asrc[u] + ko);
#pragma unroll
        for (int u = 0; u < 2; u++) cp16(base + bdst[u], bsrc[u] + ko);
        cp_commit();
    };

    issue(0); issue(1);

    const int abase = (warp_m + lane4) * TS_ROWP + lanek;
    const int bbase = TS_B + (warp_n + lane4) * TS_ROWP + lanek;

#pragma unroll
    for (int ch = 0; ch < 32; ch++) {
        cp_wait<1>();
        __syncthreads();
        const uint2* pa = smt + (ch % 3) * TS_STG + abase;
        const uint2* pb = smt + (ch % 3) * TS_STG + bbase;

#pragma unroll
        for (int kk = 0; kk < 16; kk += 8) {
            unsigned ah[MI][4], al[MI][4], bh[NI][2], bl[NI][2];
#pragma unroll
            for (int i = 0; i < MI; i++) {
                uint2 t0 = pa[i * 320 + kk];
                uint2 t1 = pa[i * 320 + 160 + kk];
                uint2 t2 = pa[i * 320 + kk + 4];
                uint2 t3 = pa[i * 320 + 160 + kk + 4];
                ah[i][0] = t0.x; al[i][0] = t0.y;
                ah[i][1] = t1.x; al[i][1] = t1.y;
                ah[i][2] = t2.x; al[i][2] = t2.y;
                ah[i][3] = t3.x; al[i][3] = t3.y;
            }
#pragma unroll
            for (int j = 0; j < NI; j++) {
                uint2 t0 = pb[j * 160 + kk];
                uint2 t1 = pb[j * 160 + kk + 4];
                bh[j][0] = t0.x; bl[j][0] = t0.y;
                bh[j][1] = t1.x; bl[j][1] = t1.y;
            }
#pragma unroll
            for (int i = 0; i < MI; i++)
#pragma unroll
                for (int j = 0; j < NI; j++) {
                    mma_bf16(acc[i][j], ah[i], bl[j]);
                    mma_bf16(acc[i][j], al[i], bh[j]);
                    mma_bf16(acc[i][j], ah[i], bh[j]);
                }
        }

        // stage (ch+2)%3 == (ch-1)%3: all readers passed this chunk's top
        // sync, so overwriting without a bottom barrier is safe.
        if (ch + 2 < 32) issue(ch + 2);
        else cp_commit();               // keep group count consistent
    }

    // ---- fused score epilogue over this warp's 32 columns ------------------
    float vv[NI][2], uu[NI][2];
#pragma unroll
    for (int j = 0; j < NI; j++)
#pragma unroll
        for (int qc = 0; qc < 2; qc++) {
            int c = n0 + warp_n + j * 8 + 2 * lanek + qc;
            vv[j][qc] = v[c];
            uu[j][qc] = Ub[c];
        }

    const int slot = blockIdx.x * 2 + (w >> 2);
#pragma unroll
    for (int i = 0; i < MI; i++)
#pragma unroll
        for (int qr = 0; qr < 2; qr++) {
            int row = m0 + warp_m + i * 16 + lane4 + qr * 8;
            int b = row & (Bq - 1);
            const float* hwr = g_hW + (size_t)b * Hq + n0 + warp_n + 2 * lanek;
            float part = 0.f;
#pragma unroll
            for (int j = 0; j < NI; j++)
#pragma unroll
                for (int qc = 0; qc < 2; qc++) {
                    float t = acc[i][j][2 * qr + qc] + uu[j][qc]
                              + hwr[j * 8 + qc];
                    part += vv[j][qc] * tanh_fast(t);
                }
            part += __shfl_xor_sync(0xffffffffu, part, 1);
            part += __shfl_xor_sync(0xffffffffu, part, 2);
            if (lanek == 0)
                g_spart[(size_t)slot * SBq + row] = part;
        }
}

// ================== 3xBF16 GEMM template (hW) ===============================
template <int BM, int BN, int BK, int WM, int WN>
__global__ void __launch_bounds__(256)
mma3bf_gemm_nt(const float* __restrict__ A, const float* __restrict__ Bm,
               float* __restrict__ C, int M, int N, int K,
               const float* __restrict__ bias)
{
    constexpr int MI = WM / 16;
    constexpr int NI = WN / 8;
    constexpr int PP = BK / 2;
    constexpr int KPP = PP + 4;
    constexpr int F4R = BK / 4;
    constexpr int RPP = 256 / F4R;

    __shared__ uint2 Aa[BM][KPP];
    __shared__ uint2 Ba[BN][KPP];

    const int tid = threadIdx.x;
    const int lane = tid & 31;
    const int w = tid >> 5;
    const int warp_m = (w % (BM / WM)) * WM;
    const int warp_n = (w / (BM / WM)) * WN;
    const int m0 = blockIdx.y * BM;
    const int n0 = blockIdx.x * BN;
    const int lrow = tid / F4R;
    const int lk4 = (tid % F4R) * 4;
    const int lp = lk4 >> 1;

    float acc[MI][NI][4];
#pragma unroll
    for (int i = 0; i < MI; i++)
#pragma unroll
        for (int j = 0; j < NI; j++)
#pragma unroll
            for (int q = 0; q < 4; q++) acc[i][j][q] = 0.f;

    for (int k0 = 0; k0 < K; k0 += BK) {
#pragma unroll
        for (int r = lrow; r < BM; r += RPP) {
            float4 vv = *reinterpret_cast<const float4*>(
                A + (size_t)(m0 + r) * K + k0 + lk4);
            float hx, lx, hy, ly, hz, lz, hw, lw;
            split_bf16(vv.x, hx, lx); split_bf16(vv.y, hy, ly);
            split_bf16(vv.z, hz, lz); split_bf16(vv.w, hw, lw);
            Aa[r][lp]     = make_uint2(pack2(hx, hy), pack2(lx, ly));
            Aa[r][lp + 1] = make_uint2(pack2(hz, hw), pack2(lz, lw));
        }
#pragma unroll
        for (int r = lrow; r < BN; r += RPP) {
            float4 vv = make_float4(0.f, 0.f, 0.f, 0.f);
            if (n0 + r < N)
                vv = *reinterpret_cast<const float4*>(
                    Bm + (size_t)(n0 + r) * K + k0 + lk4);
            float hx, lx, hy, ly, hz, lz, hw, lw;
            split_bf16(vv.x, hx, lx); split_bf16(vv.y, hy, ly);
            split_bf16(vv.z, hz, lz); split_bf16(vv.w, hw, lw);
            Ba[r][lp]     = make_uint2(pack2(hx, hy), pack2(lx, ly));
            Ba[r][lp + 1] = make_uint2(pack2(hz, hw), pack2(lz, lw));
        }
        __syncthreads();

#pragma unroll
        for (int kk = 0; kk < PP; kk += 8) {
            unsigned ah[MI][4], al[MI][4], bh[NI][2], bl[NI][2];
#pragma unroll
            for (int i = 0; i < MI; i++) {
                int r = warp_m + i * 16 + (lane >> 2);
                int cb = kk + (lane & 3);
                uint2 t0 = Aa[r][cb];      ah[i][0] = t0.x; al[i][0] = t0.y;
                uint2 t1 = Aa[r + 8][cb];  ah[i][1] = t1.x; al[i][1] = t1.y;
                uint2 t2 = Aa[r][cb + 4];  ah[i][2] = t2.x; al[i][2] = t2.y;
                uint2 t3 = Aa[r + 8][cb + 4]; ah[i][3] = t3.x; al[i][3] = t3.y;
            }
#pragma unroll
            for (int j = 0; j < NI; j++) {
                int r = warp_n + j * 8 + (lane >> 2);
                int cb = kk + (lane & 3);
                uint2 t0 = Ba[r][cb];      bh[j][0] = t0.x; bl[j][0] = t0.y;
                uint2 t1 = Ba[r][cb + 4];  bh[j][1] = t1.x; bl[j][1] = t1.y;
            }
#pragma unroll
            for (int i = 0; i < MI; i++)
#pragma unroll
                for (int j = 0; j < NI; j++) {
                    mma_bf16(acc[i][j], ah[i], bl[j]);
                    mma_bf16(acc[i][j], al[i], bh[j]);
                    mma_bf16(acc[i][j], ah[i], bh[j]);
                }
        }
        __syncthreads();
    }

#pragma unroll
    for (int i = 0; i < MI; i++)
#pragma unroll
        for (int j = 0; j < NI; j++) {
            int row = m0 + warp_m + i * 16 + (lane >> 2);
            int col = n0 + warp_n + j * 8 + 2 * (lane & 3);
#pragma unroll
            for (int q = 0; q < 4; q++) {
                int gr = row + (q >> 1) * 8;
                int gc = col + (q & 1);
                if (gc < N) {
                    float r = acc[i][j][q];
                    if (bias) r += bias[gc];
                    C[(size_t)gr * N + gc] = r;
                }
            }
        }
}

// ============ fused gates GEMM: [x2] @ [W_ih;W_hh]^T, K=2560, 3xBF16 ========
__global__ void __launch_bounds__(256)
gates_kernel(const float* __restrict__ W1, const float* __restrict__ W2,
             const float* __restrict__ b1, const float* __restrict__ b2)
{
    constexpr int BM = 64, BN = 64, BK = 32;
    constexpr int MI = 2, NI = 2;
    constexpr int PP = 16, KPP = 20;

    __shared__ uint2 Aa[BM][KPP];
    __shared__ uint2 Ba[BN][KPP];

    const int tid = threadIdx.x;
    const int lane = tid & 31;
    const int w = tid >> 5;
    const int warp_m = (w % 2) * 32;
    const int warp_n = (w / 2) * 16;
    const int n0 = blockIdx.x * BN;
    const int lrow = tid >> 3;
    const int lk4 = (tid & 7) * 4;
    const int lp = lk4 >> 1;

    float acc[MI][NI][4];
#pragma unroll
    for (int i = 0; i < MI; i++)
#pragma unroll
        for (int j = 0; j < NI; j++)
#pragma unroll
            for (int q = 0; q < 4; q++) acc[i][j][q] = 0.f;

    for (int k0 = 0; k0 < K2q; k0 += BK) {
#pragma unroll
        for (int r = lrow; r < BM; r += 32) {
            float4 vv = *reinterpret_cast<const float4*>(
                g_x2 + (size_t)r * K2q + k0 + lk4);
            float hx, lx, hy, ly, hz, lz, hw, lw;
            split_bf16(vv.x, hx, lx); split_bf16(vv.y, hy, ly);
            split_bf16(vv.z, hz, lz); split_bf16(vv.w, hw, lw);
            Aa[r][lp]     = make_uint2(pack2(hx, hy), pack2(lx, ly));
            Aa[r][lp + 1] = make_uint2(pack2(hz, hw), pack2(lz, lw));
        }
#pragma unroll
        for (int r = lrow; r < BN; r += 32) {
            const float* src = (k0 < 1536)
                ? W1 + (size_t)(n0 + r) * 1536 + k0 + lk4
                : W2 + (size_t)(n0 + r) * Hq + (k0 - 1536) + lk4;
            float4 vv = *reinterpret_cast<const float4*>(src);
            float hx, lx, hy, ly, hz, lz, hw, lw;
            split_bf16(vv.x, hx, lx); split_bf16(vv.y, hy, ly);
            split_bf16(vv.z, hz, lz); split_bf16(vv.w, hw, lw);
            Ba[r][lp]     = make_uint2(pack2(hx, hy), pack2(lx, ly));
            Ba[r][lp + 1] = make_uint2(pack2(hz, hw), pack2(lz, lw));
        }
        __syncthreads();

#pragma unroll
        for (int kk = 0; kk < PP; kk += 8) {
            unsigned ah[MI][4], al[MI][4], bh[NI][2], bl[NI][2];
#pragma unroll
            for (int i = 0; i < MI; i++) {
                int r = warp_m + i * 16 + (lane >> 2);
                int cb = kk + (lane & 3);
                uint2 t0 = Aa[r][cb];      ah[i][0] = t0.x; al[i][0] = t0.y;
                uint2 t1 = Aa[r + 8][cb];  ah[i][1] = t1.x; al[i][1] = t1.y;
                uint2 t2 = Aa[r][cb + 4];  ah[i][2] = t2.x; al[i][2] = t2.y;
                uint2 t3 = Aa[r + 8][cb + 4]; ah[i][3] = t3.x; al[i][3] = t3.y;
            }
#pragma unroll
            for (int j = 0; j < NI; j++) {
                int r = warp_n + j * 8 + (lane >> 2);
                int cb = kk + (lane & 3);
                uint2 t0 = Ba[r][cb];      bh[j][0] = t0.x; bl[j][0] = t0.y;
                uint2 t1 = Ba[r][cb + 4];  bh[j][1] = t1.x; bl[j][1] = t1.y;
            }
#pragma unroll
            for (int i = 0; i < MI; i++)
#pragma unroll
                for (int j = 0; j < NI; j++) {
                    mma_bf16(acc[i][j], ah[i], bl[j]);
                    mma_bf16(acc[i][j], al[i], bh[j]);
                    mma_bf16(acc[i][j], ah[i], bh[j]);
                }
        }
        __syncthreads();
    }

#pragma unroll
    for (int i = 0; i < MI; i++)
#pragma unroll
        for (int j = 0; j < NI; j++) {
            int row = warp_m + i * 16 + (lane >> 2);
            int col = n0 + warp_n + j * 8 + 2 * (lane & 3);
#pragma unroll
            for (int q = 0; q < 4; q++) {
                int gr = row + (q >> 1) * 8;
                int gc = col + (q & 1);
                g_gates[(size_t)gr * G4q + gc] =
                    acc[i][j][q] + b1[gc] + b2[gc];
            }
        }
}

// ====== logits GEMM: bf16, 3-stage cp.async pipelined =======================
// C[64, V] = h[64,1024] @ out_W[V,1024]^T + out_b. BM=64, BN=128, BK=32.
// fp32 staged via cp.async (ROW=40 words, conflict-free LDS.64), converted
// to bf16x2 at fragment load.
#define LG_ROW 40                       /* fp32 words per row (32 + 8 pad) */
#define LG_B (64 * LG_ROW)              /* B offset in words = 2560 */
#define LG_STG (192 * LG_ROW)           /* words per stage = 7680 */
#define LG_STGB (LG_STG * 4)            /* 30720 B */
#define LG_SMEM (3 * LG_STGB)           /* 92160 B */

__global__ void __launch_bounds__(256, 2)
logits_kernel(const float* __restrict__ A, const float* __restrict__ Bm,
              float* __restrict__ C, const float* __restrict__ bias)
{
    extern __shared__ float sml[];
    constexpr int MI = 2, NI = 4;       // warp grid 2(M)x4(N)
    const int N = Vq, K = Hq;

    const int tid = threadIdx.x;
    const int lane = tid & 31;
    const int w = tid >> 5;
    const int lane4 = lane >> 2;
    const int lanek = lane & 3;
    const int warp_m = (w & 1) * 32;
    const int warp_n = (w >> 1) * 32;
    const int n0 = blockIdx.x * 128;

    // loader: A 512 float4 -> 2/thread; B 1024 float4 -> 4/thread
    const uint32_t sb0 = smem_u32(sml);
    uint32_t adst[2], bdst[4];
    const float* asrc[2];
    const float* bsrc[4];
    int bok[4];
#pragma unroll
    for (int u = 0; u < 2; u++) {
        int i = tid + 256 * u;
        int row = i >> 3, f4 = (i & 7) * 4;
        adst[u] = (uint32_t)(row * LG_ROW + f4) * 4;
        asrc[u] = A + (size_t)row * K + f4;
    }
#pragma unroll
    for (int u = 0; u < 4; u++) {
        int i = tid + 256 * u;
        int row = i >> 3, f4 = (i & 7) * 4;
        bdst[u] = (uint32_t)(LG_B + row * LG_ROW + f4) * 4;
        bsrc[u] = Bm + (size_t)(n0 + row) * K + f4;
        bok[u] = (n0 + row) < N;
    }

    float acc[MI][NI][4];
#pragma unroll
    for (int i = 0; i < MI; i++)
#pragma unroll
        for (int j = 0; j < NI; j++)
#pragma unroll
            for (int q = 0; q < 4; q++) acc[i][j][q] = 0.f;

    auto issue = [&](int ch) {
        uint32_t base = sb0 + (uint32_t)(ch % 3) * LG_STGB;
        int ko = ch * 32;
#pragma unroll
        for (int u = 0; u < 2; u++) cp16(base + adst[u], asrc[u] + ko);
#pragma unroll
        for (int u = 0; u < 4; u++)
            cp16g(base + bdst[u], bsrc[u] + ko, bok[u]);
        cp_commit();
    };

    issue(0); issue(1);

    const int abase = (warp_m + lane4) * LG_ROW + 2 * lanek;
    const int bbase = LG_B + (warp_n + lane4) * LG_ROW + 2 * lanek;

#pragma unroll
    for (int ch = 0; ch < 32; ch++) {
        cp_wait<1>();
        __syncthreads();
        const float* pa = sml + (ch % 3) * LG_STG + abase;
        const float* pb = sml + (ch % 3) * LG_STG + bbase;

#pragma unroll
        for (int kk = 0; kk < 32; kk += 16) {
            unsigned af[MI][4], bf[NI][2];
#pragma unroll
            for (int i = 0; i < MI; i++) {
                float2 t0 = *reinterpret_cast<const float2*>(
                    pa + i * 16 * LG_ROW + kk);
                float2 t1 = *reinterpret_cast<const float2*>(
                    pa + i * 16 * LG_ROW + 8 * LG_ROW + kk);
                float2 t2 = *reinterpret_cast<const float2*>(
                    pa + i * 16 * LG_ROW + kk + 8);
                float2 t3 = *reinterpret_cast<const float2*>(
                    pa + i * 16 * LG_ROW + 8 * LG_ROW + kk + 8);
                af[i][0] = pack2(t0.x, t0.y);
                af[i][1] = pack2(t1.x, t1.y);
                af[i][2] = pack2(t2.x, t2.y);
                af[i][3] = pack2(t3.x, t3.y);
            }
#pragma unroll
            for (int j = 0; j < NI; j++) {
                float2 t0 = *reinterpret_cast<const float2*>(
                    pb + j * 8 * LG_ROW + kk);
                float2 t1 = *reinterpret_cast<const float2*>(
                    pb + j * 8 * LG_ROW + kk + 8);
                bf[j][0] = pack2(t0.x, t0.y);
                bf[j][1] = pack2(t1.x, t1.y);
            }
#pragma unroll
            for (int i = 0; i < MI; i++)
#pragma unroll
                for (int j = 0; j < NI; j++)
                    mma_bf16(acc[i][j], af[i], bf[j]);
        }

        if (ch + 2 < 32) issue(ch + 2);
        else cp_commit();
    }

#pragma unroll
    for (int i = 0; i < MI; i++)
#pragma unroll
        for (int j = 0; j < NI; j++) {
            int row = warp_m + i * 16 + lane4;
            int col = n0 + warp_n + j * 8 + 2 * lanek;
#pragma unroll
            for (int q = 0; q < 4; q++) {
                int gr = row + (q >> 1) * 8;
                int gc = col + (q & 1);
                if (gc < N)
                    C[(size_t)gr * N + gc] = acc[i][j][q] + bias[gc];
            }
        }
}

// ---------------- pointwise / reduction kernels -----------------------------
__global__ void softmax_kernel(float* __restrict__ attn_out)
{
    __shared__ float sm[Sq];
    int b = blockIdx.x, t = threadIdx.x;
    float x = 0.f;
#pragma unroll
    for (int q = 0; q < NSLOT; q++)
        x += g_spart[(size_t)q * SBq + t * Bq + b];
    sm[t] = x; __syncthreads();
    for (int o = 64; o > 0; o >>= 1) {
        if (t < o) sm[t] = fmaxf(sm[t], sm[t + o]);
        __syncthreads();
    }
    float m = sm[0];
    __syncthreads();
    float e = expf(x - m);
    sm[t] = e; __syncthreads();
    for (int o = 64; o > 0; o >>= 1) {
        if (t < o) sm[t] += sm[t + o];
        __syncthreads();
    }
    attn_out[b * Sq + t] = e / sm[0];
}

__global__ void context_kernel(const float* __restrict__ attn,
                               const float* __restrict__ enc)
{
    __shared__ float aw[Sq];
    int idx = blockIdx.x * 256 + threadIdx.x;
    int b = idx >> 10;
    int h = idx & (Hq - 1);
    if (threadIdx.x < Sq) aw[threadIdx.x] = attn[b * Sq + threadIdx.x];
    __syncthreads();
    float acc = 0.f;
#pragma unroll 8
    for (int s = 0; s < Sq; s++)
        acc = fmaf(aw[s], enc[((size_t)s * Bq + b) * Hq + h], acc);
    g_ctx[idx] = acc;
}

__global__ void xbuild_kernel(const int* __restrict__ seq,
                              const float* __restrict__ emb,
                              const float* __restrict__ h0)
{
    int idx = blockIdx.x * 256 + threadIdx.x;
    int b = idx / K2q;
    int j = idx - b * K2q;
    float val;
    if (j < Eq)            val = emb[(size_t)seq[b] * Eq + j];
    else if (j < Eq + Hq)  val = g_ctx[b * Hq + (j - Eq)];
    else                   val = h0[b * Hq + (j - Eq - Hq)];
    g_x2[idx] = val;
}

__device__ __forceinline__ float sigf(float x) { return 1.f / (1.f + expf(-x)); }

__global__ void lstm_kernel(const float* __restrict__ c0,
                            float* __restrict__ h_new,
                            float* __restrict__ c_new)
{
    int idx = blockIdx.x * 256 + threadIdx.x;
    int b = idx >> 10;
    int h = idx & (Hq - 1);
    const float* g = g_gates + ((size_t)b << 12);
    float vi = g[h];
    float vf = g[Hq + h];
    float vg = g[2 * Hq + h];
    float vo = g[3 * Hq + h];
    float c = sigf(vf) * c0[idx] + sigf(vi) * tanhf(vg);
    c_new[idx] = c;
    h_new[idx] = sigf(vo) * tanhf(c);
}

// ---- two-phase log-softmax -------------------------------------------------
__global__ void ls_partial_kernel(const float* __restrict__ out)
{
    __shared__ float red[8];
    int b = blockIdx.x, c = blockIdx.y, t = threadIdx.x;
    const float* row = out + (size_t)b * Vq;
    int j0 = c * LSC;
    int j1 = min(j0 + LSC, Vq);

    float m = -1e30f;
    for (int j = j0 + t; j < j1; j += 256) m = fmaxf(m, row[j]);
#pragma unroll
    for (int o = 16; o > 0; o >>= 1) m = fmaxf(m, __shfl_xor_sync(~0u, m, o));
    if ((t & 31) == 0) red[t >> 5] = m;
    __syncthreads();
    if (t < 32) {
        float vv = (t < 8) ? red[t] : -1e30f;
#pragma unroll
        for (int o = 4; o > 0; o >>= 1) vv = fmaxf(vv, __shfl_xor_sync(~0u, vv, o));
        if (t == 0) red[0] = vv;
    }
    __syncthreads();
    m = red[0];
    __syncthreads();

    float s = 0.f;
    for (int j = j0 + t; j < j1; j += 256) s += expf(row[j] - m);
#pragma unroll
    for (int o = 16; o > 0; o >>= 1) s += __shfl_xor_sync(~0u, s, o);
    if ((t & 31) == 0) red[t >> 5] = s;
    __syncthreads();
    if (t < 32) {
        float vv = (t < 8) ? red[t] : 0.f;
#pragma unroll
        for (int o = 4; o > 0; o >>= 1) vv += __shfl_xor_sync(~0u, vv, o);
        if (t == 0) {
            g_lsm[b * 8 + c] = m;
            g_lss[b * 8 + c] = vv;
        }
    }
}

__global__ void ls_apply_kernel(float* __restrict__ out)
{
    int b = blockIdx.x, c = blockIdx.y, t = threadIdx.x;
    float M = -1e30f;
#pragma unroll
    for (int q = 0; q < 8; q++) M = fmaxf(M, g_lsm[b * 8 + q]);
    float S = 0.f;
#pragma unroll
    for (int q = 0; q < 8; q++)
        S += g_lss[b * 8 + q] * expf(g_lsm[b * 8 + q] - M);
    float lse = M + logf(S);

    float* row = out + (size_t)b * Vq;
    int j0 = c * LSC;
    int j1 = min(j0 + LSC, Vq);
    for (int j = j0 + t; j < j1; j += 256) row[j] -= lse;
}

// ---------------------------------------------------------------------------
extern "C" void kernel_launch(void* const* d_in, const int* in_sizes, int n_in,
                              void* d_out, int out_size)
{
    const int*   seq     = (const int*)d_in[0];
    const float* h0      = (const float*)d_in[1];
    const float* c0      = (const float*)d_in[2];
    const float* enc     = (const float*)d_in[3];
    const float* emb     = (const float*)d_in[4];
    const float* W_ih    = (const float*)d_in[5];
    const float* W_hh    = (const float*)d_in[6];
    const float* b_ih    = (const float*)d_in[7];
    const float* b_hh    = (const float*)d_in[8];
    const float* attn_W  = (const float*)d_in[9];
    const float* attn_Wb = (const float*)d_in[10];
    const float* attn_U  = (const float*)d_in[11];
    const float* attn_Ub = (const float*)d_in[12];
    const float* attn_v  = (const float*)d_in[13];
    const float* out_W   = (const float*)d_in[14];
    const float* out_b   = (const float*)d_in[15];

    float* out      = (float*)d_out;
    float* o_logits = out;                          // [B, V]
    float* o_h      = out + (size_t)Bq * Vq;        // [1, B, H]
    float* o_c      = o_h + Bq * Hq;                // [1, B, H]
    float* o_attn   = o_c + Bq * Hq;                // [B, 1, S]

    float* hW;
    cudaGetSymbolAddress((void**)&hW, g_hW);

    cudaFuncSetAttribute(tgemm_score_kernel,
                         cudaFuncAttributeMaxDynamicSharedMemorySize, TS_SMEM);
    cudaFuncSetAttribute(logits_kernel,
                         cudaFuncAttributeMaxDynamicSharedMemorySize, LG_SMEM);

    // 1) hW = h0 @ attn_W^T + attn_Wb            [64, 1024]  (3xBF16, 16 CTA)
    mma3bf_gemm_nt<64, 64, 32, 32, 16><<<dim3(Hq / 64, 1), 256>>>(
        h0, attn_W, hW, Bq, Hq, Hq, attn_Wb);

    // 2) pre-split enc and U to hi/lo bf16x2 pairs (merged)
    presplit_kernel<<<(ENC4 + Hq * Hq / 4) / 256, 256>>>(enc, attn_U);

    // 3) T GEMM (pre-split, 3-stage cp.async, no bottom sync) + fused score
    tgemm_score_kernel<<<dim3(Hq / 64, SBq / 128), 256, TS_SMEM>>>(
        attn_Ub, attn_v);

    // 4) attn = softmax(reduce(spart)) -> output region
    softmax_kernel<<<Bq, Sq>>>(o_attn);

    // 5) context = attn @ enc                    [64, 1024]
    context_kernel<<<Bq * Hq / 256, 256>>>(o_attn, enc);

    // 6) x2 = [emb[seq] ; ctx ; h0]              [64, 2560]
    xbuild_kernel<<<Bq * K2q / 256, 256>>>(seq, emb, h0);

    // 7) gates = x2 @ [W_ih;W_hh]^T + biases     (fused, 64 CTA)
    gates_kernel<<<dim3(G4q / 64, 1), 256>>>(W_ih, W_hh, b_ih, b_hh);

    // 8) LSTM pointwise -> h_new, c_new in output
    lstm_kernel<<<Bq * Hq / 256, 256>>>(c0, o_h, o_c);

    // 9) logits = h_new @ out_W^T + out_b        (bf16, cp.async pipelined)
    logits_kernel<<<dim3((Vq + 127) / 128, 1), 256, LG_SMEM>>>(
        o_h, out_W, o_logits, out_b);

    // 10-11) log_softmax: partials then apply
    ls_partial_kernel<<<dim3(Bq, 8), 256>>>(o_logits);
    ls_apply_kernel<<<dim3(Bq, 8), 256>>>(o_logits);
}